// round 6
// baseline (speedup 1.0000x reference)
#include <cuda_runtime.h>

// Grouping: segment mean-pooling over sorted segment ids — single fused kernel.
//   feats: [B=8, S=8192, H=512] f32;  seg: [B, S] i32 sorted;  out: [B,G=1024,H] f32 (+counts tail)
//
// Grid = B * (S/TOK) CTAs. Chunk c of batch b owns groups g in (seg[c*TOK-1], seg[(c+1)*TOK-1]]
// (last chunk extended to G-1): a disjoint complete partition with NO duplicated feats
// reads — a straddling group is streamed entirely by its owner, the next chunk skips it.
// Boundaries found by parallel adjacent-diff on an smem id window (global binary-search
// fallback for groups longer than the lookahead).
// TOK=32 -> 2048 CTAs (~55 warps/SM) so DRAM latency is covered.

#define BB 8
#define SS 8192
#define HH 512
#define GG 1024
#define H4 (HH / 4)       // 128 float4 per row == blockDim.x
#define TOK 32            // tokens owned per CTA
#define WIN 192           // id lookahead window (covers group sizes up to ~160)
#define NCH (SS / TOK)    // 256 chunks per batch row

__global__ __launch_bounds__(128)
void group_mean_fused(const float4* __restrict__ feats4,
                      const int* __restrict__ seg,
                      float* __restrict__ out,
                      int write_counts)
{
    const int bc = blockIdx.x;
    const int b  = bc >> 8;            // / NCH
    const int c  = bc & (NCH - 1);     // % NCH
    const int t  = threadIdx.x;
    const int base = c * TOK;

    __shared__ int sid[WIN + 1];       // sid[0]=id at base-1 (or -1); sid[1+i]=id at base+i (GG past S)
    __shared__ int gstart[GG + 2];     // window-relative start pos, indexed by (g - lo)

    const int* __restrict__ srow = seg + b * SS;

    // ---- load id window ----
    for (int i = t; i < WIN; i += 128) {
        int idx = base + i;
        sid[1 + i] = (idx < SS) ? srow[idx] : GG;
    }
    if (t == 0) sid[0] = (base == 0) ? -1 : srow[base - 1];
    __syncthreads();

    const int lo = sid[0] + 1;
    int hi = sid[TOK];                         // id of last token in chunk
    if (c == NCH - 1) hi = GG - 1;             // last chunk owns trailing empty groups
    if (lo > hi) return;                       // chunk fully inside an upstream-owned group

    // entry hi+1 may stay uncovered if group hi extends past the window
    if (t == 0) gstart[hi - lo + 1] = -1;
    __syncthreads();

    // ---- parallel adjacent-diff: group g starts where ids cross g ----
    for (int i = t; i < WIN; i += 128) {
        int prev = sid[i];
        int cur  = sid[i + 1];
        int glo = max(prev + 1, lo);
        int ghi = min(cur, hi + 1);
        for (int g = glo; g <= ghi; ++g)
            gstart[g - lo] = i;
    }
    __syncthreads();

    // ---- stream each owned group ----
    const float4* __restrict__ fb = feats4 + (size_t)b * SS * H4 + t;
    float4* __restrict__ ob = (float4*)out + (size_t)b * GG * H4 + t;

    for (int g = lo; g <= hi; ++g) {
        const int start = base + gstart[g - lo];
        int ep = gstart[g - lo + 1];
        int end;
        if (ep >= 0) {
            end = base + ep;
        } else {
            // rare: group extends beyond window -> converged lower_bound of (g+1)
            int l = base + WIN, h = SS;
            while (l < h) { int m = (l + h) >> 1; if (srow[m] <= g) l = m + 1; else h = m; }
            end = l;
        }
        const int n = end - start;

        float4 acc = make_float4(0.f, 0.f, 0.f, 0.f);
        const float4* __restrict__ p = fb + (size_t)start * H4;
        int s = 0;
        for (; s + 4 <= n; s += 4) {
            float4 v0 = p[(size_t)(s + 0) * H4];
            float4 v1 = p[(size_t)(s + 1) * H4];
            float4 v2 = p[(size_t)(s + 2) * H4];
            float4 v3 = p[(size_t)(s + 3) * H4];
            acc.x += (v0.x + v1.x) + (v2.x + v3.x);
            acc.y += (v0.y + v1.y) + (v2.y + v3.y);
            acc.z += (v0.z + v1.z) + (v2.z + v3.z);
            acc.w += (v0.w + v1.w) + (v2.w + v3.w);
        }
        for (; s < n; ++s) {
            float4 v = p[(size_t)s * H4];
            acc.x += v.x; acc.y += v.y; acc.z += v.z; acc.w += v.w;
        }

        const float inv = (n > 0) ? (1.0f / (float)n) : 0.0f;
        acc.x *= inv; acc.y *= inv; acc.z *= inv; acc.w *= inv;
        ob[(size_t)g * H4] = acc;

        if (write_counts && t == 0)
            out[(size_t)BB * GG * HH + b * GG + g] = (float)n;
    }
}

extern "C" void kernel_launch(void* const* d_in, const int* in_sizes, int n_in,
                              void* d_out, int out_size)
{
    const float4* feats4 = (const float4*)d_in[0];
    const int*    seg    = (const int*)d_in[1];
    float*        out    = (float*)d_out;

    const int grouped_elems = BB * GG * HH;
    const int write_counts  = (out_size >= grouped_elems + BB * GG) ? 1 : 0;

    group_mean_fused<<<BB * NCH, 128>>>(feats4, seg, out, write_counts);
}

// round 10
// speedup vs baseline: 1.1003x; 1.1003x over previous
#include <cuda_runtime.h>

// Grouping: segment mean-pooling over sorted segment ids — single kernel,
// one CTA per (b, g), warp-cooperative 32-ary bounds search.
//   feats: [B=8, S=8192, H=512] f32;  seg: [B, S] i32 sorted
//   out:   grouped [B, G=1024, H] f32, then (if room) counts [B, G] as f32
//
// lower_bound over S=8192 in 3 rounds of 32 parallel probes (8192 -> 256 -> 8 -> 1):
// 3 dependent L1-hot loads (~few hundred cycles) instead of 13 dependent L2 probes
// or a separate boundary kernel + launch gap. Warp 0 searches g, warp 1 searches
// g+1, concurrently. Then 128 threads stream the contiguous token range
// (float4, MLP=4, fully coalesced) and scale by 1/count.

#define BB 8
#define SS 8192
#define HH 512
#define GG 1024
#define H4 (HH / 4)  // 128 float4 per row == blockDim.x

__device__ __forceinline__ int lower_bound_warp32(const int* __restrict__ row,
                                                  int target, int lane)
{
    // level 1: 32 blocks of 256; probe each block's last element
    int v = __ldg(row + lane * 256 + 255);
    unsigned m = __ballot_sync(0xffffffffu, v < target);
    int lo = __popc(m) * 256;
    if (lo == SS) return SS;                  // warp-uniform exit

    // level 2: 32 blocks of 8
    v = __ldg(row + lo + lane * 8 + 7);
    m = __ballot_sync(0xffffffffu, v < target);
    lo += __popc(m) * 8;
    if (lo == SS) return SS;                  // warp-uniform exit

    // level 3: 8 elements (all 32 lanes participate; lanes >=8 masked out of ballot)
    v = __ldg(row + lo + (lane & 7));
    m = __ballot_sync(0xffffffffu, (lane < 8) && (v < target));
    return lo + __popc(m);
}

__global__ __launch_bounds__(128, 16)
void group_mean_kernel(const float4* __restrict__ feats4,
                       const int* __restrict__ seg,
                       float* __restrict__ out,
                       int write_counts)
{
    const int bg = blockIdx.x;          // 0 .. B*G-1
    const int b  = bg >> 10;            // / G
    const int g  = bg & (GG - 1);       // % G
    const int t  = threadIdx.x;
    const int w  = t >> 5;
    const int lane = t & 31;

    __shared__ int sh_bounds[2];
    if (w < 2) {
        int r = lower_bound_warp32(seg + b * SS, g + w, lane);
        if (lane == 0) sh_bounds[w] = r;
    }
    __syncthreads();

    const int start = sh_bounds[0];
    const int end   = sh_bounds[1];
    const int cnt   = end - start;

    float4 acc = make_float4(0.f, 0.f, 0.f, 0.f);
    const float4* __restrict__ p = feats4 + ((size_t)b * SS + start) * H4 + t;

    int s = 0;
    // 4 independent LDG.128 in flight per thread
    for (; s + 4 <= cnt; s += 4) {
        float4 v0 = p[(size_t)(s + 0) * H4];
        float4 v1 = p[(size_t)(s + 1) * H4];
        float4 v2 = p[(size_t)(s + 2) * H4];
        float4 v3 = p[(size_t)(s + 3) * H4];
        acc.x += (v0.x + v1.x) + (v2.x + v3.x);
        acc.y += (v0.y + v1.y) + (v2.y + v3.y);
        acc.z += (v0.z + v1.z) + (v2.z + v3.z);
        acc.w += (v0.w + v1.w) + (v2.w + v3.w);
    }
    for (; s < cnt; ++s) {
        float4 v = p[(size_t)s * H4];
        acc.x += v.x; acc.y += v.y; acc.z += v.z; acc.w += v.w;
    }

    const float inv = (cnt > 0) ? (1.0f / (float)cnt) : 0.0f;
    acc.x *= inv; acc.y *= inv; acc.z *= inv; acc.w *= inv;

    ((float4*)out)[(size_t)bg * H4 + t] = acc;

    if (write_counts && t == 0) {
        out[(size_t)BB * GG * HH + bg] = (float)cnt;
    }
}

extern "C" void kernel_launch(void* const* d_in, const int* in_sizes, int n_in,
                              void* d_out, int out_size)
{
    const float4* feats4 = (const float4*)d_in[0];
    const int*    seg    = (const int*)d_in[1];
    float*        out    = (float*)d_out;

    const int grouped_elems = BB * GG * HH;               // 4,194,304
    const int write_counts  = (out_size >= grouped_elems + BB * GG) ? 1 : 0;

    group_mean_kernel<<<BB * GG, 128>>>(feats4, seg, out, write_counts);
}

// round 15
// speedup vs baseline: 1.1697x; 1.0631x over previous
#include <cuda_runtime.h>

// Grouping: segment mean-pooling over sorted segment ids — single kernel,
// one CTA per (b, g), predicted-window boundary scan.
//   feats: [B=8, S=8192, H=512] f32;  seg: [B, S] i32 sorted
//   out:   grouped [B, G=1024, H] f32, then (if room) counts [B, G] as f32
//
// ids ~ Uniform(0,G) sorted => lower_bound(g) ~ 8g +/- ~45 (std). Each CTA loads a
// CONTIGUOUS 385-int window around 8g (13 coalesced lines, L2-hot), finds both group
// boundaries by adjacent-diff, and verifies coverage exactly; rare misses fall back
// to a warp-cooperative 32-ary search. This replaces R10's scattered probes
// (~80 L1 wavefronts/CTA) with ~13, so the float4 stream keeps the LSU.

#define BB 8
#define SS 8192
#define HH 512
#define GG 1024
#define H4 (HH / 4)   // 128 float4 per row == blockDim.x
#define W  385        // window entries; entry i = token (8g - 185 + i)

__device__ __forceinline__ int lower_bound_warp32(const int* __restrict__ row,
                                                  int target, int lane)
{
    int v = __ldg(row + lane * 256 + 255);
    unsigned m = __ballot_sync(0xffffffffu, v < target);
    int lo = __popc(m) * 256;
    if (lo == SS) return SS;
    v = __ldg(row + lo + lane * 8 + 7);
    m = __ballot_sync(0xffffffffu, v < target);
    lo += __popc(m) * 8;
    if (lo == SS) return SS;
    v = __ldg(row + lo + (lane & 7));
    m = __ballot_sync(0xffffffffu, (lane < 8) && (v < target));
    return lo + __popc(m);
}

__global__ __launch_bounds__(128, 16)
void group_mean_kernel(const float4* __restrict__ feats4,
                       const int* __restrict__ seg,
                       float* __restrict__ out,
                       int write_counts)
{
    const int bg = blockIdx.x;          // 0 .. B*G-1
    const int b  = bg >> 10;            // / G
    const int g  = bg & (GG - 1);       // % G
    const int t  = threadIdx.x;

    __shared__ int sid[W];
    __shared__ int sh_bounds[2];

    const int* __restrict__ srow = seg + b * SS;
    const int p0 = (g << 3) - 185;      // token position of sid[0]

    // contiguous, coalesced window load with edge sentinels
    #pragma unroll
    for (int k = 0; k < 4; ++k) {
        int i = t + k * 128;            // covers 0..511 >= W
        if (i < W) {
            int p = p0 + i;
            sid[i] = (p < 0) ? -1 : ((p >= SS) ? GG : srow[p]);
        }
    }
    __syncthreads();

    // exact coverage test: both boundaries lie strictly inside the window
    const bool covered = (sid[0] < g) && (sid[W - 1] >= g + 1);

    if (covered) {
        // adjacent-diff: unique crossing for g and for g+1
        #pragma unroll
        for (int k = 0; k < 4; ++k) {
            int i = t + k * 128 + 1;    // 1..W-1
            if (i < W) {
                int a = sid[i - 1], c = sid[i];
                if (a < g && c >= g)             sh_bounds[0] = p0 + i;
                if (a < g + 1 && c >= g + 1)     sh_bounds[1] = p0 + i;
            }
        }
    } else {
        // rare tail: full 32-ary search (warp 0 -> g, warp 1 -> g+1)
        const int w = t >> 5, lane = t & 31;
        if (w < 2) {
            int r = lower_bound_warp32(srow, g + w, lane);
            if (lane == 0) sh_bounds[w] = r;
        }
    }
    __syncthreads();

    const int start = sh_bounds[0];
    const int end   = sh_bounds[1];
    const int cnt   = end - start;

    float4 acc = make_float4(0.f, 0.f, 0.f, 0.f);
    const float4* __restrict__ p = feats4 + ((size_t)b * SS + start) * H4 + t;

    int s = 0;
    for (; s + 4 <= cnt; s += 4) {
        float4 v0 = p[(size_t)(s + 0) * H4];
        float4 v1 = p[(size_t)(s + 1) * H4];
        float4 v2 = p[(size_t)(s + 2) * H4];
        float4 v3 = p[(size_t)(s + 3) * H4];
        acc.x += (v0.x + v1.x) + (v2.x + v3.x);
        acc.y += (v0.y + v1.y) + (v2.y + v3.y);
        acc.z += (v0.z + v1.z) + (v2.z + v3.z);
        acc.w += (v0.w + v1.w) + (v2.w + v3.w);
    }
    for (; s < cnt; ++s) {
        float4 v = p[(size_t)s * H4];
        acc.x += v.x; acc.y += v.y; acc.z += v.z; acc.w += v.w;
    }

    const float inv = (cnt > 0) ? (1.0f / (float)cnt) : 0.0f;
    acc.x *= inv; acc.y *= inv; acc.z *= inv; acc.w *= inv;

    ((float4*)out)[(size_t)bg * H4 + t] = acc;

    if (write_counts && t == 0) {
        out[(size_t)BB * GG * HH + bg] = (float)cnt;
    }
}

extern "C" void kernel_launch(void* const* d_in, const int* in_sizes, int n_in,
                              void* d_out, int out_size)
{
    const float4* feats4 = (const float4*)d_in[0];
    const int*    seg    = (const int*)d_in[1];
    float*        out    = (float*)d_out;

    const int grouped_elems = BB * GG * HH;               // 4,194,304
    const int write_counts  = (out_size >= grouped_elems + BB * GG) ? 1 : 0;

    group_mean_kernel<<<BB * GG, 128>>>(feats4, seg, out, write_counts);
}